// round 15
// baseline (speedup 1.0000x reference)
#include <cuda_runtime.h>
#include <math.h>
#include <stdint.h>

// ---------------------------------------------------------------------------
// Problem constants
// ---------------------------------------------------------------------------
#define BB 256
#define NN 32
#define ED 256
#define BN 8192            // B*N rows
#define MJ 31              // n-1 edges per row

// Output layout (flattened concat of the 6 reference outputs)
#define O1 0                       // att_embedding (8192,512)
#define O2 4194304                 // hard_logits[...,1] (8192,31)
#define O3 (O2 + 253952)           // unnorm_rel_dist (8192,31)
#define O4 (O3 + 253952)           // mean_entropy (1)
#define O5 (O4 + 1)                // hard_weights (256,32,31)
#define O6 (O5 + 253952)           // comb_w (flat == combined flat)

#define PI_F  3.14159274f
#define TWO_PI_F 6.28318548f

typedef unsigned long long ull;

// ---------------------------------------------------------------------------
// Device scratch (no allocations allowed)
// ---------------------------------------------------------------------------
__device__ float g_X [BN * 512];   // [ae | attn_out]  (d1 input)
__device__ float g_Y [BN * 512];   // d1 output
__device__ float g_AQ[BN * 512];   // [ai | qa]
__device__ float g_Wc[256 * 512];  // [hm1_w[:256] | Wqa]
__device__ float g_bc[512];        // [hm1_b | as1_b]
__device__ float g_W2e[256 * 2];   // hm2_w @ he_w
__device__ float g_b2e[2];         // hm2_b @ he_w + he_b
__device__ float g_ent[BN];        // per-row entropy

// ---------------------------------------------------------------------------
// Helpers
// ---------------------------------------------------------------------------
__device__ __forceinline__ float lrelu(float x) { return x >= 0.f ? x : 0.01f * x; }

__device__ __forceinline__ float wrapf(float a) {
    float w = fmodf(a + PI_F, TWO_PI_F);
    if (w < 0.f) w += TWO_PI_F;
    return w - PI_F;
}

// Packed dual fp32 FMA (FFMA2) — 2 exact rn FMAs per issue slot.
__device__ __forceinline__ ull fma2(ull a, ull b, ull c) {
    ull d;
    asm("fma.rn.f32x2 %0, %1, %2, %3;" : "=l"(d) : "l"(a), "l"(b), "l"(c));
    return d;
}

// Generic threefry2x32 (20 rounds), KAT-verified on-device in R7.
__device__ __forceinline__ void tf2x32g(unsigned k0, unsigned k1,
                                        unsigned x0, unsigned x1,
                                        unsigned& y0, unsigned& y1) {
    const unsigned k2 = 0x1BD11BDAu ^ k0 ^ k1;
    x0 += k0; x1 += k1;
#define TFR(r) { x0 += x1; x1 = (x1 << (r)) | (x1 >> (32 - (r))); x1 ^= x0; }
    TFR(13) TFR(15) TFR(26) TFR(6)   x0 += k1; x1 += k2 + 1u;
    TFR(17) TFR(29) TFR(16) TFR(24)  x0 += k2; x1 += k0 + 2u;
    TFR(13) TFR(15) TFR(26) TFR(6)   x0 += k0; x1 += k1 + 3u;
    TFR(17) TFR(29) TFR(16) TFR(24)  x0 += k1; x1 += k2 + 4u;
    TFR(13) TFR(15) TFR(26) TFR(6)   x0 += k2; x1 += k0 + 5u;
#undef TFR
    y0 = x0; y1 = x1;
}

// Partitionable threefry (JAX default), key (0,42): bits[i] = HIGH word y0
// of the 64-bit block tf(hi(i)=0, lo(i)=i).   (verified PASS in R9)
__device__ __forceinline__ unsigned jax_bits_partitionable(unsigned idx) {
    unsigned y0, y1;
    tf2x32g(0u, 42u, 0u, idx, y0, y1);
    return y0;
}

// jax.random.uniform float conversion: minval=1e-6, maxval=1.0
__device__ __forceinline__ float jax_uniform(unsigned bits) {
    float f = __uint_as_float((bits >> 9) | 0x3F800000u) - 1.0f;
    float u = f * (1.0f - 1e-6f) + 1e-6f;
    return fmaxf(1e-6f, u);
}

// ---------------------------------------------------------------------------
// Fold kernels (tiny, once per launch)  — verified bit-identical in R3/R4
// ---------------------------------------------------------------------------
__global__ void k_fold_small(const float* __restrict__ hm2_w,
                             const float* __restrict__ hm2_b,
                             const float* __restrict__ he_w,
                             const float* __restrict__ he_b,
                             const float* __restrict__ hm1_b,
                             const float* __restrict__ as1_b) {
    int t = threadIdx.x;
    if (t < 256) {
        float a0 = 0.f, a1 = 0.f;
        for (int k = 0; k < 256; k++) {
            float hv = hm2_w[t * 256 + k];
            a0 += hv * he_w[k * 2 + 0];
            a1 += hv * he_w[k * 2 + 1];
        }
        g_W2e[t * 2 + 0] = a0;
        g_W2e[t * 2 + 1] = a1;
        g_bc[t] = hm1_b[t];
    } else {
        g_bc[t] = as1_b[t - 256];
        if (t < 258) {
            int e = t - 256;
            float a = 0.f;
            for (int k = 0; k < 256; k++) a += hm2_b[k] * he_w[k * 2 + e];
            g_b2e[e] = a + he_b[e];
        }
    }
}

__global__ void k_fold_wc(const float* __restrict__ hm1_w,
                          const float* __restrict__ q_w,
                          const float* __restrict__ as1_w) {
    int k = blockIdx.x;
    int c = threadIdx.x;
    if (c < 256) {
        g_Wc[k * 512 + c] = hm1_w[k * 256 + c];
    } else {
        int cc = c - 256;
        float a = 0.f;
        for (int m = 0; m < 256; m++)
            a += q_w[k * 256 + m] * as1_w[m * 256 + cc];
        g_Wc[k * 512 + c] = a;
    }
}

// ---------------------------------------------------------------------------
// Agent embedding MLP: emb[:,4:9] -> 128 (lrelu) -> 256 (lrelu) -> g_X[:, :256]
// ---------------------------------------------------------------------------
__global__ void __launch_bounds__(256) k_agent(const float* __restrict__ emb,
                                               const float* __restrict__ e1w,
                                               const float* __restrict__ e1b,
                                               const float* __restrict__ e2w,
                                               const float* __restrict__ e2b) {
    __shared__ float h[8][128];
    int r0 = blockIdx.x * 8;
    int t = threadIdx.x;
    for (int idx = t; idx < 1024; idx += 256) {
        int row = idx >> 7, k = idx & 127;
        const float* x = emb + (r0 + row) * 11 + 4;
        float a = e1b[k];
#pragma unroll
        for (int f = 0; f < 5; f++) a += x[f] * e1w[f * 128 + k];
        h[row][k] = lrelu(a);
    }
    __syncthreads();
    int c = t;
    float acc[8] = {0, 0, 0, 0, 0, 0, 0, 0};
    for (int k = 0; k < 128; k++) {
        float w = e2w[k * 256 + c];
#pragma unroll
        for (int row = 0; row < 8; row++) acc[row] += h[row][k] * w;
    }
    float bias = e2b[c];
#pragma unroll
    for (int row = 0; row < 8; row++)
        g_X[(r0 + row) * 512 + c] = lrelu(acc[row] + bias);
}

// ---------------------------------------------------------------------------
// Generic tiled fp32 GEMM: C = act(A[M x K, lda] @ W[K x N] + bias)
// (R10 version — at scalar-FFMA issue floor for the AQ/d1/d2 launches)
// ---------------------------------------------------------------------------
__global__ void __launch_bounds__(256) gemm_tile(const float* __restrict__ A, int lda,
                                                 const float* __restrict__ W, int N,
                                                 const float* __restrict__ bias,
                                                 float* __restrict__ C, int ldc,
                                                 int K, int act) {
    __shared__ float As[16][65];
    __shared__ float Bs[16][64];
    int m0 = blockIdx.y * 64, n0 = blockIdx.x * 64;
    int t = threadIdx.x;
    int tx = t & 15, ty = t >> 4;
    float acc[4][4] = {};
    for (int k0 = 0; k0 < K; k0 += 16) {
        for (int idx = t; idx < 1024; idx += 256) {
            int m = idx >> 4, k = idx & 15;
            As[k][m] = A[(m0 + m) * lda + k0 + k];
        }
        for (int idx = t; idx < 1024; idx += 256) {
            int k = idx >> 6, n = idx & 63;
            Bs[k][n] = W[(k0 + k) * N + n0 + n];
        }
        __syncthreads();
#pragma unroll
        for (int k = 0; k < 16; k++) {
            float a0 = As[k][ty * 4 + 0];
            float a1 = As[k][ty * 4 + 1];
            float a2 = As[k][ty * 4 + 2];
            float a3 = As[k][ty * 4 + 3];
            float4 bv = *reinterpret_cast<const float4*>(&Bs[k][tx * 4]);
            acc[0][0] += a0 * bv.x; acc[0][1] += a0 * bv.y; acc[0][2] += a0 * bv.z; acc[0][3] += a0 * bv.w;
            acc[1][0] += a1 * bv.x; acc[1][1] += a1 * bv.y; acc[1][2] += a1 * bv.z; acc[1][3] += a1 * bv.w;
            acc[2][0] += a2 * bv.x; acc[2][1] += a2 * bv.y; acc[2][2] += a2 * bv.z; acc[2][3] += a2 * bv.w;
            acc[3][0] += a3 * bv.x; acc[3][1] += a3 * bv.y; acc[3][2] += a3 * bv.z; acc[3][3] += a3 * bv.w;
        }
        __syncthreads();
    }
#pragma unroll
    for (int im = 0; im < 4; im++) {
        int m = m0 + ty * 4 + im;
#pragma unroll
        for (int in_ = 0; in_ < 4; in_++) {
            int n = n0 + tx * 4 + in_;
            float v = acc[im][in_] + (bias ? bias[n] : 0.f);
            if (act == 1) v = fmaxf(v, 0.f);
            else if (act == 2) v = lrelu(v);
            C[m * ldc + n] = v;
        }
    }
}

// ---------------------------------------------------------------------------
// Fused per-(b,i) kernel — FFMA2 score GEMM (B from L2), high occupancy.
// smem ~36 KB, __launch_bounds__(256,4) -> 4 CTAs/SM (32 warps).
// ---------------------------------------------------------------------------
#define E10S 12   // padded e10 row stride (float4-friendly)

struct EdgeSmem {
    float kf[32 * 256];   // k_feat plain (row 31 zero-padded)          32 KB
    float qa[256];
    float ai[256];
    float as2[256];
    float ag[32 * 8];
    float e10[32 * E10S]; // padded rows (12 floats, last 2 unused)
    float hl[32 * 2];
    float scores[32];
    float comb[32];
};

__global__ void __launch_bounds__(256, 4) k_edge(
    const float* __restrict__ emb,
    const float* __restrict__ as1_w,
    const float* __restrict__ as2_w,
    const float* __restrict__ as2_b,
    const float* __restrict__ kw_g,
    const float* __restrict__ vw_g,
    const float* __restrict__ vb_g,
    const float* __restrict__ hm1_w,
    float* __restrict__ out) {
    extern __shared__ char smem_raw[];
    EdgeSmem* s = reinterpret_cast<EdgeSmem*>(smem_raw);
    const int r = blockIdx.x;
    const int b = r >> 5, i = r & 31;
    const int t = threadIdx.x;
    const int lane = t & 31, w = t >> 5;
    const float* as1_low = as1_w + 256 * 256;
    const float* hm1_low = hm1_w + 256 * 256;

    s->ai[t] = g_AQ[r * 512 + t];
    s->qa[t] = g_AQ[r * 512 + 256 + t];
    s->as2[t] = as2_w[t];
    if (t < 32) {
        const float* e = emb + (b * 32 + t) * 11;
        s->ag[t * 8 + 0] = e[0];  s->ag[t * 8 + 1] = e[1];
        s->ag[t * 8 + 2] = e[2];  s->ag[t * 8 + 3] = e[3];
        s->ag[t * 8 + 4] = e[7];  s->ag[t * 8 + 5] = e[8];
        s->ag[t * 8 + 6] = e[9];  s->ag[t * 8 + 7] = e[10];
    }
    __syncthreads();

    // ---- edge / goal features + unnorm dist output ----
    if (t < MJ) {
        int jj = t;
        int j = jj + (jj >= i ? 1 : 0);
        float pix = s->ag[i * 8 + 0], piy = s->ag[i * 8 + 1];
        float hix = s->ag[i * 8 + 2], hiy = s->ag[i * 8 + 3];
        float dx = s->ag[j * 8 + 0] - pix, dy = s->ag[j * 8 + 1] - piy;
        float dist = sqrtf(dx * dx + dy * dy);
        float ha = atan2f(hiy, hix);
        float ang = wrapf(atan2f(dy, dx) - ha);
        float gx = s->ag[j * 8 + 6] - pix, gy = s->ag[j * 8 + 7] - piy;
        float gd = sqrtf(gx * gx + gy * gy);
        float ga = wrapf(atan2f(gy, gx) - ha);
        float* e10 = &s->e10[jj * E10S];
        e10[0] = dist / 12.0f;
        e10[1] = cosf(ang);  e10[2] = sinf(ang);
        e10[3] = s->ag[j * 8 + 2];  e10[4] = s->ag[j * 8 + 3];
        e10[5] = s->ag[j * 8 + 4];  e10[6] = s->ag[j * 8 + 5];
        e10[7] = gd;  e10[8] = cosf(ga);  e10[9] = sinf(ga);
        e10[10] = 0.f;  e10[11] = 0.f;
        out[O3 + r * 31 + jj] = dist;
    }
    __syncthreads();

    // ---- k_feat = lrelu(e10 @ k_w) into smem (plain, pad row 31) ----
    {
        float kw[10];
#pragma unroll
        for (int f = 0; f < 10; f++) kw[f] = kw_g[f * 256 + t];
        for (int jj = 0; jj < MJ; jj++) {
            const float* e = &s->e10[jj * E10S];
            float4 p0 = *reinterpret_cast<const float4*>(e);
            float4 p1 = *reinterpret_cast<const float4*>(e + 4);
            float2 p2 = *reinterpret_cast<const float2*>(e + 8);
            float a = p0.x * kw[0] + p0.y * kw[1] + p0.z * kw[2] + p0.w * kw[3]
                    + p1.x * kw[4] + p1.y * kw[5] + p1.z * kw[6] + p1.w * kw[7]
                    + p2.x * kw[8] + p2.y * kw[9];
            s->kf[jj * 256 + t] = lrelu(a);
        }
        s->kf[31 * 256 + t] = 0.f;
    }

    // ---- hard logits via folded W2e: warp w handles edges w, w+8, ... ----
    for (int jj = w; jj < MJ; jj += 8) {
        const float* e7 = &s->e10[jj * E10S];
        float f0 = e7[0], f1 = e7[1], f2 = e7[2], f3 = e7[3];
        float f4 = e7[4], f5 = e7[5], f6 = e7[6];
        float a0 = 0.f, a1 = 0.f;
#pragma unroll
        for (int u = 0; u < 8; u++) {
            int c = lane + 32 * u;
            float h = s->ai[c]
                + f0 * hm1_low[0 * 256 + c] + f1 * hm1_low[1 * 256 + c]
                + f2 * hm1_low[2 * 256 + c] + f3 * hm1_low[3 * 256 + c]
                + f4 * hm1_low[4 * 256 + c] + f5 * hm1_low[5 * 256 + c]
                + f6 * hm1_low[6 * 256 + c];
            h = fmaxf(h, 0.f);
            a0 += h * g_W2e[c * 2 + 0];
            a1 += h * g_W2e[c * 2 + 1];
        }
#pragma unroll
        for (int o = 16; o; o >>= 1) {
            a0 += __shfl_xor_sync(0xffffffffu, a0, o);
            a1 += __shfl_xor_sync(0xffffffffu, a1, o);
        }
        if (lane == 0) {
            float l1 = a1 + g_b2e[1];
            s->hl[jj * 2 + 0] = a0 + g_b2e[0];
            s->hl[jj * 2 + 1] = l1;
            out[O2 + r * 31 + jj] = l1;
        }
    }
    __syncthreads();   // kf complete before GEMM reads cross-warp rows

    // ---- score GEMM (FFMA2, B from L2): hidden = relu(qa + kf@as1_low).as2
    const int j0 = (t >> 5) * 4;
    const int cA = (t & 31) * 4;
    const int cB = cA + 128;
    ull acc2[4][4] = {};   // [row][pair]: (cA,cA+1),(cA+2,3),(cB,cB+1),(cB+2,3)

    const float* kfr0 = &s->kf[(j0 + 0) * 256];
    const float* kfr1 = &s->kf[(j0 + 1) * 256];
    const float* kfr2 = &s->kf[(j0 + 2) * 256];
    const float* kfr3 = &s->kf[(j0 + 3) * 256];

#pragma unroll 4
    for (int k = 0; k < 256; k++) {
        ulonglong2 bA = *reinterpret_cast<const ulonglong2*>(as1_low + k * 256 + cA);
        ulonglong2 bB = *reinterpret_cast<const ulonglong2*>(as1_low + k * 256 + cB);
        float v0 = kfr0[k], v1 = kfr1[k], v2 = kfr2[k], v3 = kfr3[k];
        float2 f0 = make_float2(v0, v0);
        float2 f1 = make_float2(v1, v1);
        float2 f2 = make_float2(v2, v2);
        float2 f3 = make_float2(v3, v3);
        ull a0 = *reinterpret_cast<ull*>(&f0);
        ull a1 = *reinterpret_cast<ull*>(&f1);
        ull a2 = *reinterpret_cast<ull*>(&f2);
        ull a3 = *reinterpret_cast<ull*>(&f3);
        acc2[0][0] = fma2(a0, bA.x, acc2[0][0]);
        acc2[0][1] = fma2(a0, bA.y, acc2[0][1]);
        acc2[0][2] = fma2(a0, bB.x, acc2[0][2]);
        acc2[0][3] = fma2(a0, bB.y, acc2[0][3]);
        acc2[1][0] = fma2(a1, bA.x, acc2[1][0]);
        acc2[1][1] = fma2(a1, bA.y, acc2[1][1]);
        acc2[1][2] = fma2(a1, bB.x, acc2[1][2]);
        acc2[1][3] = fma2(a1, bB.y, acc2[1][3]);
        acc2[2][0] = fma2(a2, bA.x, acc2[2][0]);
        acc2[2][1] = fma2(a2, bA.y, acc2[2][1]);
        acc2[2][2] = fma2(a2, bB.x, acc2[2][2]);
        acc2[2][3] = fma2(a2, bB.y, acc2[2][3]);
        acc2[3][0] = fma2(a3, bA.x, acc2[3][0]);
        acc2[3][1] = fma2(a3, bA.y, acc2[3][1]);
        acc2[3][2] = fma2(a3, bB.x, acc2[3][2]);
        acc2[3][3] = fma2(a3, bB.y, acc2[3][3]);
    }

    float as2b0 = as2_b[0];
    float qaA[4], qaB[4], s2A[4], s2B[4];
#pragma unroll
    for (int c = 0; c < 4; c++) {
        qaA[c] = s->qa[cA + c];  qaB[c] = s->qa[cB + c];
        s2A[c] = s->as2[cA + c]; s2B[c] = s->as2[cB + c];
    }
#pragma unroll
    for (int jj = 0; jj < 4; jj++) {
        float2 pA0 = *reinterpret_cast<const float2*>(&acc2[jj][0]);
        float2 pA1 = *reinterpret_cast<const float2*>(&acc2[jj][1]);
        float2 pB0 = *reinterpret_cast<const float2*>(&acc2[jj][2]);
        float2 pB1 = *reinterpret_cast<const float2*>(&acc2[jj][3]);
        float aAcc[4] = {pA0.x, pA0.y, pA1.x, pA1.y};
        float bAcc[4] = {pB0.x, pB0.y, pB1.x, pB1.y};
        float sp = 0.f;
#pragma unroll
        for (int c = 0; c < 4; c++) {
            float hA = fmaxf(qaA[c] + aAcc[c], 0.f);
            float hB = fmaxf(qaB[c] + bAcc[c], 0.f);
            sp += hA * s2A[c] + hB * s2B[c];
        }
#pragma unroll
        for (int o = 16; o; o >>= 1) sp += __shfl_xor_sync(0xffffffffu, sp, o);
        if (lane == 0) s->scores[j0 + jj] = sp + as2b0;
    }
    __syncthreads();

    // ---- gumbel softmax, mask, masked softmax, entropy (warp 0) ----
    if (t < 32) {
        int jj = t;
        bool valid = jj < MJ;
        float maskf = 0.f, ms = -1e30f;
        if (valid) {
            unsigned f0 = 2u * ((unsigned)r * 31u + (unsigned)jj);
            unsigned b0 = jax_bits_partitionable(f0);
            unsigned b1_ = jax_bits_partitionable(f0 + 1u);
            float u0 = jax_uniform(b0), u1 = jax_uniform(b1_);
            float gz0 = -logf(-logf(u0)), gz1 = -logf(-logf(u1));
            float z0 = (s->hl[jj * 2 + 0] + gz0) / 0.5f;
            float z1 = (s->hl[jj * 2 + 1] + gz1) / 0.5f;
            float mz = fmaxf(z0, z1);
            float e0 = expf(z0 - mz), e1 = expf(z1 - mz);
            float hw = e1 / (e0 + e1);
            out[O5 + r * 31 + jj] = hw;
            maskf = hw > 0.5f ? 1.f : 0.f;
            float score = s->scores[jj];
            ms = maskf > 0.f ? score : -1e30f;
        }
        float cnt = maskf;
#pragma unroll
        for (int o = 16; o; o >>= 1) cnt += __shfl_xor_sync(0xffffffffu, cnt, o);
        float mx = ms;
#pragma unroll
        for (int o = 16; o; o >>= 1) mx = fmaxf(mx, __shfl_xor_sync(0xffffffffu, mx, o));
        float ev = valid ? expf(ms - mx) : 0.f;
        float se = ev;
#pragma unroll
        for (int o = 16; o; o >>= 1) se += __shfl_xor_sync(0xffffffffu, se, o);
        float soft = (cnt < 1e-6f) ? 0.f : ev / se;
        float comb = soft * maskf;
        float cs = comb;
#pragma unroll
        for (int o = 16; o; o >>= 1) cs += __shfl_xor_sync(0xffffffffu, cs, o);
        float cwn = comb / (cs + 1e-6f);
        float entc = valid ? cwn * logf(cwn + 1e-6f) : 0.f;
        float ent = entc;
#pragma unroll
        for (int o = 16; o; o >>= 1) ent += __shfl_xor_sync(0xffffffffu, ent, o);
        if (jj == 0) g_ent[r] = -ent;
        if (valid) out[O6 + r * 31 + jj] = comb;
        s->comb[jj] = valid ? comb : 0.f;
    }
    __syncthreads();

    // ---- attn_out = sum_j comb_j * lrelu(e10_j @ v_w + v_b) ----
    {
        float vw[10];
#pragma unroll
        for (int f = 0; f < 10; f++) vw[f] = vw_g[f * 256 + t];
        float vb = vb_g[t];
        float a2 = 0.f;
        for (int jj = 0; jj < MJ; jj++) {
            const float* e = &s->e10[jj * E10S];
            float4 p0 = *reinterpret_cast<const float4*>(e);
            float4 p1 = *reinterpret_cast<const float4*>(e + 4);
            float2 p2 = *reinterpret_cast<const float2*>(e + 8);
            float a = vb
                + p0.x * vw[0] + p0.y * vw[1] + p0.z * vw[2] + p0.w * vw[3]
                + p1.x * vw[4] + p1.y * vw[5] + p1.z * vw[6] + p1.w * vw[7]
                + p2.x * vw[8] + p2.y * vw[9];
            a2 += s->comb[jj] * lrelu(a);
        }
        g_X[r * 512 + 256 + t] = a2;
    }
}

// ---------------------------------------------------------------------------
// Deterministic entropy mean reduction
// ---------------------------------------------------------------------------
__global__ void k_final(float* __restrict__ out) {
    __shared__ float sh[256];
    int t = threadIdx.x;
    float a = 0.f;
    for (int i = t; i < BN; i += 256) a += g_ent[i];
    sh[t] = a;
    __syncthreads();
    for (int o = 128; o; o >>= 1) {
        if (t < o) sh[t] += sh[t + o];
        __syncthreads();
    }
    if (t == 0) out[O4] = sh[0] * (1.0f / 8192.0f);
}

// ---------------------------------------------------------------------------
// Launch
// ---------------------------------------------------------------------------
extern "C" void kernel_launch(void* const* d_in, const int* in_sizes, int n_in,
                              void* d_out, int out_size) {
    (void)in_sizes; (void)n_in; (void)out_size;
    const float* emb   = (const float*)d_in[0];
    const float* e1_w  = (const float*)d_in[1];
    const float* e1_b  = (const float*)d_in[2];
    const float* e2_w  = (const float*)d_in[3];
    const float* e2_b  = (const float*)d_in[4];
    const float* hm1_w = (const float*)d_in[5];
    const float* hm1_b = (const float*)d_in[6];
    const float* hm2_w = (const float*)d_in[7];
    const float* hm2_b = (const float*)d_in[8];
    const float* he_w  = (const float*)d_in[9];
    const float* he_b  = (const float*)d_in[10];
    const float* q_w   = (const float*)d_in[11];
    const float* k_w   = (const float*)d_in[12];
    const float* v_w   = (const float*)d_in[13];
    const float* v_b   = (const float*)d_in[14];
    const float* as1_w = (const float*)d_in[15];
    const float* as1_b = (const float*)d_in[16];
    const float* as2_w = (const float*)d_in[17];
    const float* as2_b = (const float*)d_in[18];
    const float* d1_w  = (const float*)d_in[19];
    const float* d1_b  = (const float*)d_in[20];
    const float* d2_w  = (const float*)d_in[21];
    const float* d2_b  = (const float*)d_in[22];
    float* out = (float*)d_out;

    float *pX, *pY, *pAQ, *pWc, *pbc;
    cudaGetSymbolAddress((void**)&pX, g_X);
    cudaGetSymbolAddress((void**)&pY, g_Y);
    cudaGetSymbolAddress((void**)&pAQ, g_AQ);
    cudaGetSymbolAddress((void**)&pWc, g_Wc);
    cudaGetSymbolAddress((void**)&pbc, g_bc);

    cudaFuncSetAttribute(k_edge, cudaFuncAttributeMaxDynamicSharedMemorySize,
                         (int)sizeof(EdgeSmem));

    k_fold_small<<<1, 512>>>(hm2_w, hm2_b, he_w, he_b, hm1_b, as1_b);
    k_fold_wc<<<256, 512>>>(hm1_w, q_w, as1_w);
    k_agent<<<BN / 8, 256>>>(emb, e1_w, e1_b, e2_w, e2_b);

    // AQ = ae @ [hm1_w[:256] | Wqa] + [hm1_b | as1_b]   (M=8192, K=256, N=512)
    gemm_tile<<<dim3(512 / 64, BN / 64), 256>>>(pX, 512, pWc, 512, pbc, pAQ, 512, 256, 0);

    k_edge<<<BN, 256, sizeof(EdgeSmem)>>>(emb, as1_w, as2_w, as2_b,
                                          k_w, v_w, v_b, hm1_w, out);
    k_final<<<1, 256>>>(out);

    gemm_tile<<<dim3(512 / 64, BN / 64), 256>>>(pX, 512, d1_w, 512, d1_b, pY, 512, 512, 2);
    gemm_tile<<<dim3(512 / 64, BN / 64), 256>>>(pY, 512, d2_w, 512, d2_b, out + O1, 512, 512, 2);
}

// round 16
// speedup vs baseline: 1.1541x; 1.1541x over previous
#include <cuda_runtime.h>
#include <math.h>
#include <stdint.h>

// ---------------------------------------------------------------------------
// Problem constants
// ---------------------------------------------------------------------------
#define BB 256
#define NN 32
#define ED 256
#define BN 8192            // B*N rows
#define MJ 31              // n-1 edges per row

// Output layout (flattened concat of the 6 reference outputs)
#define O1 0                       // att_embedding (8192,512)
#define O2 4194304                 // hard_logits[...,1] (8192,31)
#define O3 (O2 + 253952)           // unnorm_rel_dist (8192,31)
#define O4 (O3 + 253952)           // mean_entropy (1)
#define O5 (O4 + 1)                // hard_weights (256,32,31)
#define O6 (O5 + 253952)           // comb_w (flat == combined flat)

#define PI_F  3.14159274f
#define TWO_PI_F 6.28318548f

typedef unsigned long long ull;

// ---------------------------------------------------------------------------
// Device scratch (no allocations allowed)
// ---------------------------------------------------------------------------
__device__ float g_X [BN * 512];   // [ae | attn_out]  (d1 input)
__device__ float g_Y [BN * 512];   // d1 output
__device__ float g_AQ[BN * 512];   // [ai | qa]
__device__ float g_Wc[256 * 512];  // [hm1_w[:256] | Wqa]
__device__ float g_bc[512];        // [hm1_b | as1_b]
__device__ float g_W2e[256 * 2];   // hm2_w @ he_w
__device__ float g_b2e[2];         // hm2_b @ he_w + he_b
__device__ float g_ent[BN];        // per-row entropy

// ---------------------------------------------------------------------------
// Helpers
// ---------------------------------------------------------------------------
__device__ __forceinline__ float lrelu(float x) { return x >= 0.f ? x : 0.01f * x; }

__device__ __forceinline__ float wrapf(float a) {
    float w = fmodf(a + PI_F, TWO_PI_F);
    if (w < 0.f) w += TWO_PI_F;
    return w - PI_F;
}

// Packed dual fp32 FMA (FFMA2) — 2 exact rn FMAs per issue slot.
__device__ __forceinline__ ull fma2(ull a, ull b, ull c) {
    ull d;
    asm("fma.rn.f32x2 %0, %1, %2, %3;" : "=l"(d) : "l"(a), "l"(b), "l"(c));
    return d;
}

// Generic threefry2x32 (20 rounds), KAT-verified on-device in R7.
__device__ __forceinline__ void tf2x32g(unsigned k0, unsigned k1,
                                        unsigned x0, unsigned x1,
                                        unsigned& y0, unsigned& y1) {
    const unsigned k2 = 0x1BD11BDAu ^ k0 ^ k1;
    x0 += k0; x1 += k1;
#define TFR(r) { x0 += x1; x1 = (x1 << (r)) | (x1 >> (32 - (r))); x1 ^= x0; }
    TFR(13) TFR(15) TFR(26) TFR(6)   x0 += k1; x1 += k2 + 1u;
    TFR(17) TFR(29) TFR(16) TFR(24)  x0 += k2; x1 += k0 + 2u;
    TFR(13) TFR(15) TFR(26) TFR(6)   x0 += k0; x1 += k1 + 3u;
    TFR(17) TFR(29) TFR(16) TFR(24)  x0 += k1; x1 += k2 + 4u;
    TFR(13) TFR(15) TFR(26) TFR(6)   x0 += k2; x1 += k0 + 5u;
#undef TFR
    y0 = x0; y1 = x1;
}

// Partitionable threefry (JAX default), key (0,42): bits[i] = HIGH word y0
// of the 64-bit block tf(hi(i)=0, lo(i)=i).   (verified PASS in R9)
__device__ __forceinline__ unsigned jax_bits_partitionable(unsigned idx) {
    unsigned y0, y1;
    tf2x32g(0u, 42u, 0u, idx, y0, y1);
    return y0;
}

// jax.random.uniform float conversion: minval=1e-6, maxval=1.0
__device__ __forceinline__ float jax_uniform(unsigned bits) {
    float f = __uint_as_float((bits >> 9) | 0x3F800000u) - 1.0f;
    float u = f * (1.0f - 1e-6f) + 1e-6f;
    return fmaxf(1e-6f, u);
}

// ---------------------------------------------------------------------------
// Fold kernels (tiny, once per launch)  — verified bit-identical in R3/R4
// ---------------------------------------------------------------------------
__global__ void k_fold_small(const float* __restrict__ hm2_w,
                             const float* __restrict__ hm2_b,
                             const float* __restrict__ he_w,
                             const float* __restrict__ he_b,
                             const float* __restrict__ hm1_b,
                             const float* __restrict__ as1_b) {
    int t = threadIdx.x;
    if (t < 256) {
        float a0 = 0.f, a1 = 0.f;
        for (int k = 0; k < 256; k++) {
            float hv = hm2_w[t * 256 + k];
            a0 += hv * he_w[k * 2 + 0];
            a1 += hv * he_w[k * 2 + 1];
        }
        g_W2e[t * 2 + 0] = a0;
        g_W2e[t * 2 + 1] = a1;
        g_bc[t] = hm1_b[t];
    } else {
        g_bc[t] = as1_b[t - 256];
        if (t < 258) {
            int e = t - 256;
            float a = 0.f;
            for (int k = 0; k < 256; k++) a += hm2_b[k] * he_w[k * 2 + e];
            g_b2e[e] = a + he_b[e];
        }
    }
}

__global__ void k_fold_wc(const float* __restrict__ hm1_w,
                          const float* __restrict__ q_w,
                          const float* __restrict__ as1_w) {
    int k = blockIdx.x;
    int c = threadIdx.x;
    if (c < 256) {
        g_Wc[k * 512 + c] = hm1_w[k * 256 + c];
    } else {
        int cc = c - 256;
        float a = 0.f;
        for (int m = 0; m < 256; m++)
            a += q_w[k * 256 + m] * as1_w[m * 256 + cc];
        g_Wc[k * 512 + c] = a;
    }
}

// ---------------------------------------------------------------------------
// Agent embedding MLP: emb[:,4:9] -> 128 (lrelu) -> 256 (lrelu) -> g_X[:, :256]
// ---------------------------------------------------------------------------
__global__ void __launch_bounds__(256) k_agent(const float* __restrict__ emb,
                                               const float* __restrict__ e1w,
                                               const float* __restrict__ e1b,
                                               const float* __restrict__ e2w,
                                               const float* __restrict__ e2b) {
    __shared__ float h[8][128];
    int r0 = blockIdx.x * 8;
    int t = threadIdx.x;
    for (int idx = t; idx < 1024; idx += 256) {
        int row = idx >> 7, k = idx & 127;
        const float* x = emb + (r0 + row) * 11 + 4;
        float a = e1b[k];
#pragma unroll
        for (int f = 0; f < 5; f++) a += x[f] * e1w[f * 128 + k];
        h[row][k] = lrelu(a);
    }
    __syncthreads();
    int c = t;
    float acc[8] = {0, 0, 0, 0, 0, 0, 0, 0};
    for (int k = 0; k < 128; k++) {
        float w = e2w[k * 256 + c];
#pragma unroll
        for (int row = 0; row < 8; row++) acc[row] += h[row][k] * w;
    }
    float bias = e2b[c];
#pragma unroll
    for (int row = 0; row < 8; row++)
        g_X[(r0 + row) * 512 + c] = lrelu(acc[row] + bias);
}

// ---------------------------------------------------------------------------
// Generic tiled fp32 GEMM: C = act(A[M x K, lda] @ W[K x N] + bias)
// (R10 version — at scalar-FFMA issue floor for the AQ/d1/d2 launches)
// ---------------------------------------------------------------------------
__global__ void __launch_bounds__(256) gemm_tile(const float* __restrict__ A, int lda,
                                                 const float* __restrict__ W, int N,
                                                 const float* __restrict__ bias,
                                                 float* __restrict__ C, int ldc,
                                                 int K, int act) {
    __shared__ float As[16][65];
    __shared__ float Bs[16][64];
    int m0 = blockIdx.y * 64, n0 = blockIdx.x * 64;
    int t = threadIdx.x;
    int tx = t & 15, ty = t >> 4;
    float acc[4][4] = {};
    for (int k0 = 0; k0 < K; k0 += 16) {
        for (int idx = t; idx < 1024; idx += 256) {
            int m = idx >> 4, k = idx & 15;
            As[k][m] = A[(m0 + m) * lda + k0 + k];
        }
        for (int idx = t; idx < 1024; idx += 256) {
            int k = idx >> 6, n = idx & 63;
            Bs[k][n] = W[(k0 + k) * N + n0 + n];
        }
        __syncthreads();
#pragma unroll
        for (int k = 0; k < 16; k++) {
            float a0 = As[k][ty * 4 + 0];
            float a1 = As[k][ty * 4 + 1];
            float a2 = As[k][ty * 4 + 2];
            float a3 = As[k][ty * 4 + 3];
            float4 bv = *reinterpret_cast<const float4*>(&Bs[k][tx * 4]);
            acc[0][0] += a0 * bv.x; acc[0][1] += a0 * bv.y; acc[0][2] += a0 * bv.z; acc[0][3] += a0 * bv.w;
            acc[1][0] += a1 * bv.x; acc[1][1] += a1 * bv.y; acc[1][2] += a1 * bv.z; acc[1][3] += a1 * bv.w;
            acc[2][0] += a2 * bv.x; acc[2][1] += a2 * bv.y; acc[2][2] += a2 * bv.z; acc[2][3] += a2 * bv.w;
            acc[3][0] += a3 * bv.x; acc[3][1] += a3 * bv.y; acc[3][2] += a3 * bv.z; acc[3][3] += a3 * bv.w;
        }
        __syncthreads();
    }
#pragma unroll
    for (int im = 0; im < 4; im++) {
        int m = m0 + ty * 4 + im;
#pragma unroll
        for (int in_ = 0; in_ < 4; in_++) {
            int n = n0 + tx * 4 + in_;
            float v = acc[im][in_] + (bias ? bias[n] : 0.f);
            if (act == 1) v = fmaxf(v, 0.f);
            else if (act == 2) v = lrelu(v);
            C[m * ldc + n] = v;
        }
    }
}

// ---------------------------------------------------------------------------
// Fused per-(b,i) kernel — R14 base (FFMA2 + smem-staged B, 3 CTAs/SM)
// + interchanged hard-logits + padded/vectorized e10.
// ---------------------------------------------------------------------------
#define E10S 12   // padded e10 row stride (float4-friendly)

struct EdgeSmem {
    float kf[32 * 256];   // k_feat plain (row 31 zero-padded)          32 KB
    float bs[32 * 256];   // staged as1_low chunk (32 k x 256 cols)     32 KB
    float qa[256];
    float ai[256];
    float as2[256];
    float ag[32 * 8];
    float e10[32 * E10S];
    float hl[32 * 2];
    float scores[32];
    float comb[32];
};

__global__ void __launch_bounds__(256, 3) k_edge(
    const float* __restrict__ emb,
    const float* __restrict__ as1_w,
    const float* __restrict__ as2_w,
    const float* __restrict__ as2_b,
    const float* __restrict__ kw_g,
    const float* __restrict__ vw_g,
    const float* __restrict__ vb_g,
    const float* __restrict__ hm1_w,
    float* __restrict__ out) {
    extern __shared__ char smem_raw[];
    EdgeSmem* s = reinterpret_cast<EdgeSmem*>(smem_raw);
    const int r = blockIdx.x;
    const int b = r >> 5, i = r & 31;
    const int t = threadIdx.x;
    const int lane = t & 31, w = t >> 5;
    const float* as1_low = as1_w + 256 * 256;
    const float* hm1_low = hm1_w + 256 * 256;

    s->ai[t] = g_AQ[r * 512 + t];
    s->qa[t] = g_AQ[r * 512 + 256 + t];
    s->as2[t] = as2_w[t];
    if (t < 32) {
        const float* e = emb + (b * 32 + t) * 11;
        s->ag[t * 8 + 0] = e[0];  s->ag[t * 8 + 1] = e[1];
        s->ag[t * 8 + 2] = e[2];  s->ag[t * 8 + 3] = e[3];
        s->ag[t * 8 + 4] = e[7];  s->ag[t * 8 + 5] = e[8];
        s->ag[t * 8 + 6] = e[9];  s->ag[t * 8 + 7] = e[10];
    }
    __syncthreads();

    // ---- edge / goal features + unnorm dist output ----
    if (t < MJ) {
        int jj = t;
        int j = jj + (jj >= i ? 1 : 0);
        float pix = s->ag[i * 8 + 0], piy = s->ag[i * 8 + 1];
        float hix = s->ag[i * 8 + 2], hiy = s->ag[i * 8 + 3];
        float dx = s->ag[j * 8 + 0] - pix, dy = s->ag[j * 8 + 1] - piy;
        float dist = sqrtf(dx * dx + dy * dy);
        float ha = atan2f(hiy, hix);
        float ang = wrapf(atan2f(dy, dx) - ha);
        float gx = s->ag[j * 8 + 6] - pix, gy = s->ag[j * 8 + 7] - piy;
        float gd = sqrtf(gx * gx + gy * gy);
        float ga = wrapf(atan2f(gy, gx) - ha);
        float* e10 = &s->e10[jj * E10S];
        e10[0] = dist / 12.0f;
        e10[1] = cosf(ang);  e10[2] = sinf(ang);
        e10[3] = s->ag[j * 8 + 2];  e10[4] = s->ag[j * 8 + 3];
        e10[5] = s->ag[j * 8 + 4];  e10[6] = s->ag[j * 8 + 5];
        e10[7] = gd;  e10[8] = cosf(ga);  e10[9] = sinf(ga);
        e10[10] = 0.f;  e10[11] = 0.f;
        out[O3 + r * 31 + jj] = dist;
    }
    __syncthreads();

    // ---- k_feat = lrelu(e10 @ k_w) into smem (plain, pad row 31) ----
    {
        float kw[10];
#pragma unroll
        for (int f = 0; f < 10; f++) kw[f] = kw_g[f * 256 + t];
        for (int jj = 0; jj < MJ; jj++) {
            const float* e = &s->e10[jj * E10S];
            float4 p0 = *reinterpret_cast<const float4*>(e);
            float4 p1 = *reinterpret_cast<const float4*>(e + 4);
            float2 p2 = *reinterpret_cast<const float2*>(e + 8);
            float a = p0.x * kw[0] + p0.y * kw[1] + p0.z * kw[2] + p0.w * kw[3]
                    + p1.x * kw[4] + p1.y * kw[5] + p1.z * kw[6] + p1.w * kw[7]
                    + p2.x * kw[8] + p2.y * kw[9];
            s->kf[jj * 256 + t] = lrelu(a);
        }
        s->kf[31 * 256 + t] = 0.f;
    }

    // ---- hard logits via folded W2e: interchanged (u outer, jj inner) ----
    // Warp w handles edges jj = w + 8*q (q = 0..3); per-jj sum order over u
    // is unchanged, so results are bit-identical to the jj-outer form.
    {
        float e7r[4][7];
#pragma unroll
        for (int q = 0; q < 4; q++) {
            int jj = w + 8 * q;
            const float* e = &s->e10[(jj < MJ ? jj : 0) * E10S];
            float4 p0 = *reinterpret_cast<const float4*>(e);
            float4 p1 = *reinterpret_cast<const float4*>(e + 4);
            e7r[q][0] = p0.x; e7r[q][1] = p0.y; e7r[q][2] = p0.z; e7r[q][3] = p0.w;
            e7r[q][4] = p1.x; e7r[q][5] = p1.y; e7r[q][6] = p1.z;
        }
        float a0[4] = {0.f, 0.f, 0.f, 0.f};
        float a1[4] = {0.f, 0.f, 0.f, 0.f};
#pragma unroll
        for (int u = 0; u < 8; u++) {
            int c = lane + 32 * u;
            float w0 = hm1_low[0 * 256 + c];
            float w1 = hm1_low[1 * 256 + c];
            float w2 = hm1_low[2 * 256 + c];
            float w3 = hm1_low[3 * 256 + c];
            float w4 = hm1_low[4 * 256 + c];
            float w5 = hm1_low[5 * 256 + c];
            float w6 = hm1_low[6 * 256 + c];
            float aiv = s->ai[c];
            float w20 = g_W2e[c * 2 + 0];
            float w21 = g_W2e[c * 2 + 1];
#pragma unroll
            for (int q = 0; q < 4; q++) {
                float h = aiv
                    + e7r[q][0] * w0 + e7r[q][1] * w1 + e7r[q][2] * w2
                    + e7r[q][3] * w3 + e7r[q][4] * w4 + e7r[q][5] * w5
                    + e7r[q][6] * w6;
                h = fmaxf(h, 0.f);
                a0[q] += h * w20;
                a1[q] += h * w21;
            }
        }
#pragma unroll
        for (int q = 0; q < 4; q++) {
#pragma unroll
            for (int o = 16; o; o >>= 1) {
                a0[q] += __shfl_xor_sync(0xffffffffu, a0[q], o);
                a1[q] += __shfl_xor_sync(0xffffffffu, a1[q], o);
            }
            int jj = w + 8 * q;
            if (lane == 0 && jj < MJ) {
                float l1 = a1[q] + g_b2e[1];
                s->hl[jj * 2 + 0] = a0[q] + g_b2e[0];
                s->hl[jj * 2 + 1] = l1;
                out[O2 + r * 31 + jj] = l1;
            }
        }
    }

    // ---- score GEMM (FFMA2, smem-staged B): hidden = relu(qa+kf@as1_low).as2
    const int j0 = (t >> 5) * 4;
    const int cA = (t & 31) * 4;
    const int cB = cA + 128;
    ull acc2[4][4] = {};   // [row][pair]: (cA,cA+1),(cA+2,3),(cB,cB+1),(cB+2,3)
    const int c4 = (t & 63) * 4;   // staging column group
    const int kb = t >> 6;         // staging k offset (0..3)

    for (int k0 = 0; k0 < 256; k0 += 32) {
        __syncthreads();   // previous chunk consumed (also orders kf on 1st iter)
#pragma unroll
        for (int kk = kb; kk < 32; kk += 4) {
            *reinterpret_cast<float4*>(&s->bs[kk * 256 + c4]) =
                *reinterpret_cast<const float4*>(&as1_low[(k0 + kk) * 256 + c4]);
        }
        __syncthreads();
#pragma unroll 8
        for (int kk = 0; kk < 32; kk++) {
            float v0 = s->kf[(j0 + 0) * 256 + k0 + kk];
            float v1 = s->kf[(j0 + 1) * 256 + k0 + kk];
            float v2 = s->kf[(j0 + 2) * 256 + k0 + kk];
            float v3 = s->kf[(j0 + 3) * 256 + k0 + kk];
            float2 f0 = make_float2(v0, v0);
            float2 f1 = make_float2(v1, v1);
            float2 f2 = make_float2(v2, v2);
            float2 f3 = make_float2(v3, v3);
            ull a0 = *reinterpret_cast<ull*>(&f0);
            ull a1 = *reinterpret_cast<ull*>(&f1);
            ull a2 = *reinterpret_cast<ull*>(&f2);
            ull a3 = *reinterpret_cast<ull*>(&f3);
            ulonglong2 bA = *reinterpret_cast<const ulonglong2*>(&s->bs[kk * 256 + cA]);
            ulonglong2 bB = *reinterpret_cast<const ulonglong2*>(&s->bs[kk * 256 + cB]);
            acc2[0][0] = fma2(a0, bA.x, acc2[0][0]);
            acc2[0][1] = fma2(a0, bA.y, acc2[0][1]);
            acc2[0][2] = fma2(a0, bB.x, acc2[0][2]);
            acc2[0][3] = fma2(a0, bB.y, acc2[0][3]);
            acc2[1][0] = fma2(a1, bA.x, acc2[1][0]);
            acc2[1][1] = fma2(a1, bA.y, acc2[1][1]);
            acc2[1][2] = fma2(a1, bB.x, acc2[1][2]);
            acc2[1][3] = fma2(a1, bB.y, acc2[1][3]);
            acc2[2][0] = fma2(a2, bA.x, acc2[2][0]);
            acc2[2][1] = fma2(a2, bA.y, acc2[2][1]);
            acc2[2][2] = fma2(a2, bB.x, acc2[2][2]);
            acc2[2][3] = fma2(a2, bB.y, acc2[2][3]);
            acc2[3][0] = fma2(a3, bA.x, acc2[3][0]);
            acc2[3][1] = fma2(a3, bA.y, acc2[3][1]);
            acc2[3][2] = fma2(a3, bB.x, acc2[3][2]);
            acc2[3][3] = fma2(a3, bB.y, acc2[3][3]);
        }
    }

    float as2b0 = as2_b[0];
    float qaA[4], qaB[4], s2A[4], s2B[4];
#pragma unroll
    for (int c = 0; c < 4; c++) {
        qaA[c] = s->qa[cA + c];  qaB[c] = s->qa[cB + c];
        s2A[c] = s->as2[cA + c]; s2B[c] = s->as2[cB + c];
    }
#pragma unroll
    for (int jj = 0; jj < 4; jj++) {
        float2 pA0 = *reinterpret_cast<const float2*>(&acc2[jj][0]);
        float2 pA1 = *reinterpret_cast<const float2*>(&acc2[jj][1]);
        float2 pB0 = *reinterpret_cast<const float2*>(&acc2[jj][2]);
        float2 pB1 = *reinterpret_cast<const float2*>(&acc2[jj][3]);
        float aAcc[4] = {pA0.x, pA0.y, pA1.x, pA1.y};
        float bAcc[4] = {pB0.x, pB0.y, pB1.x, pB1.y};
        float sp = 0.f;
#pragma unroll
        for (int c = 0; c < 4; c++) {
            float hA = fmaxf(qaA[c] + aAcc[c], 0.f);
            float hB = fmaxf(qaB[c] + bAcc[c], 0.f);
            sp += hA * s2A[c] + hB * s2B[c];
        }
#pragma unroll
        for (int o = 16; o; o >>= 1) sp += __shfl_xor_sync(0xffffffffu, sp, o);
        if (lane == 0) s->scores[j0 + jj] = sp + as2b0;
    }
    __syncthreads();

    // ---- gumbel softmax, mask, masked softmax, entropy (warp 0) ----
    if (t < 32) {
        int jj = t;
        bool valid = jj < MJ;
        float maskf = 0.f, ms = -1e30f;
        if (valid) {
            unsigned f0 = 2u * ((unsigned)r * 31u + (unsigned)jj);
            unsigned b0 = jax_bits_partitionable(f0);
            unsigned b1_ = jax_bits_partitionable(f0 + 1u);
            float u0 = jax_uniform(b0), u1 = jax_uniform(b1_);
            float gz0 = -logf(-logf(u0)), gz1 = -logf(-logf(u1));
            float z0 = (s->hl[jj * 2 + 0] + gz0) / 0.5f;
            float z1 = (s->hl[jj * 2 + 1] + gz1) / 0.5f;
            float mz = fmaxf(z0, z1);
            float e0 = expf(z0 - mz), e1 = expf(z1 - mz);
            float hw = e1 / (e0 + e1);
            out[O5 + r * 31 + jj] = hw;
            maskf = hw > 0.5f ? 1.f : 0.f;
            float score = s->scores[jj];
            ms = maskf > 0.f ? score : -1e30f;
        }
        float cnt = maskf;
#pragma unroll
        for (int o = 16; o; o >>= 1) cnt += __shfl_xor_sync(0xffffffffu, cnt, o);
        float mx = ms;
#pragma unroll
        for (int o = 16; o; o >>= 1) mx = fmaxf(mx, __shfl_xor_sync(0xffffffffu, mx, o));
        float ev = valid ? expf(ms - mx) : 0.f;
        float se = ev;
#pragma unroll
        for (int o = 16; o; o >>= 1) se += __shfl_xor_sync(0xffffffffu, se, o);
        float soft = (cnt < 1e-6f) ? 0.f : ev / se;
        float comb = soft * maskf;
        float cs = comb;
#pragma unroll
        for (int o = 16; o; o >>= 1) cs += __shfl_xor_sync(0xffffffffu, cs, o);
        float cwn = comb / (cs + 1e-6f);
        float entc = valid ? cwn * logf(cwn + 1e-6f) : 0.f;
        float ent = entc;
#pragma unroll
        for (int o = 16; o; o >>= 1) ent += __shfl_xor_sync(0xffffffffu, ent, o);
        if (jj == 0) g_ent[r] = -ent;
        if (valid) out[O6 + r * 31 + jj] = comb;
        s->comb[jj] = valid ? comb : 0.f;
    }
    __syncthreads();

    // ---- attn_out = sum_j comb_j * lrelu(e10_j @ v_w + v_b) ----
    {
        float vw[10];
#pragma unroll
        for (int f = 0; f < 10; f++) vw[f] = vw_g[f * 256 + t];
        float vb = vb_g[t];
        float a2 = 0.f;
        for (int jj = 0; jj < MJ; jj++) {
            const float* e = &s->e10[jj * E10S];
            float4 p0 = *reinterpret_cast<const float4*>(e);
            float4 p1 = *reinterpret_cast<const float4*>(e + 4);
            float2 p2 = *reinterpret_cast<const float2*>(e + 8);
            float a = vb
                + p0.x * vw[0] + p0.y * vw[1] + p0.z * vw[2] + p0.w * vw[3]
                + p1.x * vw[4] + p1.y * vw[5] + p1.z * vw[6] + p1.w * vw[7]
                + p2.x * vw[8] + p2.y * vw[9];
            a2 += s->comb[jj] * lrelu(a);
        }
        g_X[r * 512 + 256 + t] = a2;
    }
}

// ---------------------------------------------------------------------------
// Deterministic entropy mean reduction
// ---------------------------------------------------------------------------
__global__ void k_final(float* __restrict__ out) {
    __shared__ float sh[256];
    int t = threadIdx.x;
    float a = 0.f;
    for (int i = t; i < BN; i += 256) a += g_ent[i];
    sh[t] = a;
    __syncthreads();
    for (int o = 128; o; o >>= 1) {
        if (t < o) sh[t] += sh[t + o];
        __syncthreads();
    }
    if (t == 0) out[O4] = sh[0] * (1.0f / 8192.0f);
}

// ---------------------------------------------------------------------------
// Launch
// ---------------------------------------------------------------------------
extern "C" void kernel_launch(void* const* d_in, const int* in_sizes, int n_in,
                              void* d_out, int out_size) {
    (void)in_sizes; (void)n_in; (void)out_size;
    const float* emb   = (const float*)d_in[0];
    const float* e1_w  = (const float*)d_in[1];
    const float* e1_b  = (const float*)d_in[2];
    const float* e2_w  = (const float*)d_in[3];
    const float* e2_b  = (const float*)d_in[4];
    const float* hm1_w = (const float*)d_in[5];
    const float* hm1_b = (const float*)d_in[6];
    const float* hm2_w = (const float*)d_in[7];
    const float* hm2_b = (const float*)d_in[8];
    const float* he_w  = (const float*)d_in[9];
    const float* he_b  = (const float*)d_in[10];
    const float* q_w   = (const float*)d_in[11];
    const float* k_w   = (const float*)d_in[12];
    const float* v_w   = (const float*)d_in[13];
    const float* v_b   = (const float*)d_in[14];
    const float* as1_w = (const float*)d_in[15];
    const float* as1_b = (const float*)d_in[16];
    const float* as2_w = (const float*)d_in[17];
    const float* as2_b = (const float*)d_in[18];
    const float* d1_w  = (const float*)d_in[19];
    const float* d1_b  = (const float*)d_in[20];
    const float* d2_w  = (const float*)d_in[21];
    const float* d2_b  = (const float*)d_in[22];
    float* out = (float*)d_out;

    float *pX, *pY, *pAQ, *pWc, *pbc;
    cudaGetSymbolAddress((void**)&pX, g_X);
    cudaGetSymbolAddress((void**)&pY, g_Y);
    cudaGetSymbolAddress((void**)&pAQ, g_AQ);
    cudaGetSymbolAddress((void**)&pWc, g_Wc);
    cudaGetSymbolAddress((void**)&pbc, g_bc);

    cudaFuncSetAttribute(k_edge, cudaFuncAttributeMaxDynamicSharedMemorySize,
                         (int)sizeof(EdgeSmem));

    k_fold_small<<<1, 512>>>(hm2_w, hm2_b, he_w, he_b, hm1_b, as1_b);
    k_fold_wc<<<256, 512>>>(hm1_w, q_w, as1_w);
    k_agent<<<BN / 8, 256>>>(emb, e1_w, e1_b, e2_w, e2_b);

    // AQ = ae @ [hm1_w[:256] | Wqa] + [hm1_b | as1_b]   (M=8192, K=256, N=512)
    gemm_tile<<<dim3(512 / 64, BN / 64), 256>>>(pX, 512, pWc, 512, pbc, pAQ, 512, 256, 0);

    k_edge<<<BN, 256, sizeof(EdgeSmem)>>>(emb, as1_w, as2_w, as2_b,
                                          k_w, v_w, v_b, hm1_w, out);
    k_final<<<1, 256>>>(out);

    gemm_tile<<<dim3(512 / 64, BN / 64), 256>>>(pX, 512, d1_w, 512, d1_b, pY, 512, 512, 2);
    gemm_tile<<<dim3(512 / 64, BN / 64), 256>>>(pY, 512, d2_w, 512, d2_b, out + O1, 512, 512, 2);
}

// round 17
// speedup vs baseline: 1.2296x; 1.0654x over previous
#include <cuda_runtime.h>
#include <math.h>
#include <stdint.h>

// ---------------------------------------------------------------------------
// Problem constants
// ---------------------------------------------------------------------------
#define BB 256
#define NN 32
#define ED 256
#define BN 8192            // B*N rows
#define MJ 31              // n-1 edges per row

// Output layout (flattened concat of the 6 reference outputs)
#define O1 0                       // att_embedding (8192,512)
#define O2 4194304                 // hard_logits[...,1] (8192,31)
#define O3 (O2 + 253952)           // unnorm_rel_dist (8192,31)
#define O4 (O3 + 253952)           // mean_entropy (1)
#define O5 (O4 + 1)                // hard_weights (256,32,31)
#define O6 (O5 + 253952)           // comb_w (flat == combined flat)

#define PI_F  3.14159274f
#define TWO_PI_F 6.28318548f

typedef unsigned long long ull;

// ---------------------------------------------------------------------------
// Device scratch (no allocations allowed)
// ---------------------------------------------------------------------------
__device__ float g_X [BN * 512];   // [ae | attn_out]  (d1 input)
__device__ float g_Y [BN * 512];   // d1 output
__device__ float g_AQ[BN * 512];   // [ai | qa]
__device__ float g_Wc[256 * 512];  // [hm1_w[:256] | Wqa]
__device__ float g_bc[512];        // [hm1_b | as1_b]
__device__ float g_W2e[256 * 2];   // hm2_w @ he_w
__device__ float g_b2e[2];         // hm2_b @ he_w + he_b
__device__ float g_ent[BN];        // per-row entropy

// ---------------------------------------------------------------------------
// Helpers
// ---------------------------------------------------------------------------
__device__ __forceinline__ float lrelu(float x) { return x >= 0.f ? x : 0.01f * x; }

__device__ __forceinline__ float wrapf(float a) {
    float w = fmodf(a + PI_F, TWO_PI_F);
    if (w < 0.f) w += TWO_PI_F;
    return w - PI_F;
}

// Packed dual fp32 FMA (FFMA2) — 2 exact rn FMAs per issue slot.
__device__ __forceinline__ ull fma2(ull a, ull b, ull c) {
    ull d;
    asm("fma.rn.f32x2 %0, %1, %2, %3;" : "=l"(d) : "l"(a), "l"(b), "l"(c));
    return d;
}

// Generic threefry2x32 (20 rounds), KAT-verified on-device in R7.
__device__ __forceinline__ void tf2x32g(unsigned k0, unsigned k1,
                                        unsigned x0, unsigned x1,
                                        unsigned& y0, unsigned& y1) {
    const unsigned k2 = 0x1BD11BDAu ^ k0 ^ k1;
    x0 += k0; x1 += k1;
#define TFR(r) { x0 += x1; x1 = (x1 << (r)) | (x1 >> (32 - (r))); x1 ^= x0; }
    TFR(13) TFR(15) TFR(26) TFR(6)   x0 += k1; x1 += k2 + 1u;
    TFR(17) TFR(29) TFR(16) TFR(24)  x0 += k2; x1 += k0 + 2u;
    TFR(13) TFR(15) TFR(26) TFR(6)   x0 += k0; x1 += k1 + 3u;
    TFR(17) TFR(29) TFR(16) TFR(24)  x0 += k1; x1 += k2 + 4u;
    TFR(13) TFR(15) TFR(26) TFR(6)   x0 += k2; x1 += k0 + 5u;
#undef TFR
    y0 = x0; y1 = x1;
}

// Partitionable threefry (JAX default), key (0,42): bits[i] = HIGH word y0
// of the 64-bit block tf(hi(i)=0, lo(i)=i).   (verified PASS in R9)
__device__ __forceinline__ unsigned jax_bits_partitionable(unsigned idx) {
    unsigned y0, y1;
    tf2x32g(0u, 42u, 0u, idx, y0, y1);
    return y0;
}

// jax.random.uniform float conversion: minval=1e-6, maxval=1.0
__device__ __forceinline__ float jax_uniform(unsigned bits) {
    float f = __uint_as_float((bits >> 9) | 0x3F800000u) - 1.0f;
    float u = f * (1.0f - 1e-6f) + 1e-6f;
    return fmaxf(1e-6f, u);
}

// ---------------------------------------------------------------------------
// Fold kernels (tiny, once per launch)  — verified bit-identical in R3/R4
// ---------------------------------------------------------------------------
__global__ void k_fold_small(const float* __restrict__ hm2_w,
                             const float* __restrict__ hm2_b,
                             const float* __restrict__ he_w,
                             const float* __restrict__ he_b,
                             const float* __restrict__ hm1_b,
                             const float* __restrict__ as1_b) {
    int t = threadIdx.x;
    if (t < 256) {
        float a0 = 0.f, a1 = 0.f;
        for (int k = 0; k < 256; k++) {
            float hv = hm2_w[t * 256 + k];
            a0 += hv * he_w[k * 2 + 0];
            a1 += hv * he_w[k * 2 + 1];
        }
        g_W2e[t * 2 + 0] = a0;
        g_W2e[t * 2 + 1] = a1;
        g_bc[t] = hm1_b[t];
    } else {
        g_bc[t] = as1_b[t - 256];
        if (t < 258) {
            int e = t - 256;
            float a = 0.f;
            for (int k = 0; k < 256; k++) a += hm2_b[k] * he_w[k * 2 + e];
            g_b2e[e] = a + he_b[e];
        }
    }
}

__global__ void k_fold_wc(const float* __restrict__ hm1_w,
                          const float* __restrict__ q_w,
                          const float* __restrict__ as1_w) {
    int k = blockIdx.x;
    int c = threadIdx.x;
    if (c < 256) {
        g_Wc[k * 512 + c] = hm1_w[k * 256 + c];
    } else {
        int cc = c - 256;
        float a = 0.f;
        for (int m = 0; m < 256; m++)
            a += q_w[k * 256 + m] * as1_w[m * 256 + cc];
        g_Wc[k * 512 + c] = a;
    }
}

// ---------------------------------------------------------------------------
// Agent embedding MLP: emb[:,4:9] -> 128 (lrelu) -> 256 (lrelu) -> g_X[:, :256]
// ---------------------------------------------------------------------------
__global__ void __launch_bounds__(256) k_agent(const float* __restrict__ emb,
                                               const float* __restrict__ e1w,
                                               const float* __restrict__ e1b,
                                               const float* __restrict__ e2w,
                                               const float* __restrict__ e2b) {
    __shared__ float h[8][128];
    int r0 = blockIdx.x * 8;
    int t = threadIdx.x;
    for (int idx = t; idx < 1024; idx += 256) {
        int row = idx >> 7, k = idx & 127;
        const float* x = emb + (r0 + row) * 11 + 4;
        float a = e1b[k];
#pragma unroll
        for (int f = 0; f < 5; f++) a += x[f] * e1w[f * 128 + k];
        h[row][k] = lrelu(a);
    }
    __syncthreads();
    int c = t;
    float acc[8] = {0, 0, 0, 0, 0, 0, 0, 0};
    for (int k = 0; k < 128; k++) {
        float w = e2w[k * 256 + c];
#pragma unroll
        for (int row = 0; row < 8; row++) acc[row] += h[row][k] * w;
    }
    float bias = e2b[c];
#pragma unroll
    for (int row = 0; row < 8; row++)
        g_X[(r0 + row) * 512 + c] = lrelu(acc[row] + bias);
}

// ---------------------------------------------------------------------------
// Generic tiled fp32 GEMM: C = act(A[M x K, lda] @ W[K x N] + bias)
// (R10 version — at scalar-FFMA issue floor for the AQ/d1/d2 launches)
// ---------------------------------------------------------------------------
__global__ void __launch_bounds__(256) gemm_tile(const float* __restrict__ A, int lda,
                                                 const float* __restrict__ W, int N,
                                                 const float* __restrict__ bias,
                                                 float* __restrict__ C, int ldc,
                                                 int K, int act) {
    __shared__ float As[16][65];
    __shared__ float Bs[16][64];
    int m0 = blockIdx.y * 64, n0 = blockIdx.x * 64;
    int t = threadIdx.x;
    int tx = t & 15, ty = t >> 4;
    float acc[4][4] = {};
    for (int k0 = 0; k0 < K; k0 += 16) {
        for (int idx = t; idx < 1024; idx += 256) {
            int m = idx >> 4, k = idx & 15;
            As[k][m] = A[(m0 + m) * lda + k0 + k];
        }
        for (int idx = t; idx < 1024; idx += 256) {
            int k = idx >> 6, n = idx & 63;
            Bs[k][n] = W[(k0 + k) * N + n0 + n];
        }
        __syncthreads();
#pragma unroll
        for (int k = 0; k < 16; k++) {
            float a0 = As[k][ty * 4 + 0];
            float a1 = As[k][ty * 4 + 1];
            float a2 = As[k][ty * 4 + 2];
            float a3 = As[k][ty * 4 + 3];
            float4 bv = *reinterpret_cast<const float4*>(&Bs[k][tx * 4]);
            acc[0][0] += a0 * bv.x; acc[0][1] += a0 * bv.y; acc[0][2] += a0 * bv.z; acc[0][3] += a0 * bv.w;
            acc[1][0] += a1 * bv.x; acc[1][1] += a1 * bv.y; acc[1][2] += a1 * bv.z; acc[1][3] += a1 * bv.w;
            acc[2][0] += a2 * bv.x; acc[2][1] += a2 * bv.y; acc[2][2] += a2 * bv.z; acc[2][3] += a2 * bv.w;
            acc[3][0] += a3 * bv.x; acc[3][1] += a3 * bv.y; acc[3][2] += a3 * bv.z; acc[3][3] += a3 * bv.w;
        }
        __syncthreads();
    }
#pragma unroll
    for (int im = 0; im < 4; im++) {
        int m = m0 + ty * 4 + im;
#pragma unroll
        for (int in_ = 0; in_ < 4; in_++) {
            int n = n0 + tx * 4 + in_;
            float v = acc[im][in_] + (bias ? bias[n] : 0.f);
            if (act == 1) v = fmaxf(v, 0.f);
            else if (act == 2) v = lrelu(v);
            C[m * ldc + n] = v;
        }
    }
}

// ---------------------------------------------------------------------------
// Fused per-(b,i) kernel — FFMA2 + smem-staged B (R14 base), float4 A
// broadcasts to cut crossbar traffic 12 -> 9 cycles per warp per k.
// ---------------------------------------------------------------------------
#define E10S 12   // padded e10 row stride (float4-friendly)

struct EdgeSmem {
    float kf[32 * 256];   // k_feat plain (row 31 zero-padded)          32 KB
    float bs[32 * 256];   // staged as1_low chunk (32 k x 256 cols)     32 KB
    float qa[256];
    float ai[256];
    float as2[256];
    float ag[32 * 8];
    float e10[32 * E10S];
    float hl[32 * 2];
    float scores[32];
    float comb[32];
};

__global__ void __launch_bounds__(256, 3) k_edge(
    const float* __restrict__ emb,
    const float* __restrict__ as1_w,
    const float* __restrict__ as2_w,
    const float* __restrict__ as2_b,
    const float* __restrict__ kw_g,
    const float* __restrict__ vw_g,
    const float* __restrict__ vb_g,
    const float* __restrict__ hm1_w,
    float* __restrict__ out) {
    extern __shared__ char smem_raw[];
    EdgeSmem* s = reinterpret_cast<EdgeSmem*>(smem_raw);
    const int r = blockIdx.x;
    const int b = r >> 5, i = r & 31;
    const int t = threadIdx.x;
    const int lane = t & 31, w = t >> 5;
    const float* as1_low = as1_w + 256 * 256;
    const float* hm1_low = hm1_w + 256 * 256;

    s->ai[t] = g_AQ[r * 512 + t];
    s->qa[t] = g_AQ[r * 512 + 256 + t];
    s->as2[t] = as2_w[t];
    if (t < 32) {
        const float* e = emb + (b * 32 + t) * 11;
        s->ag[t * 8 + 0] = e[0];  s->ag[t * 8 + 1] = e[1];
        s->ag[t * 8 + 2] = e[2];  s->ag[t * 8 + 3] = e[3];
        s->ag[t * 8 + 4] = e[7];  s->ag[t * 8 + 5] = e[8];
        s->ag[t * 8 + 6] = e[9];  s->ag[t * 8 + 7] = e[10];
    }
    __syncthreads();

    // ---- edge / goal features + unnorm dist output ----
    if (t < MJ) {
        int jj = t;
        int j = jj + (jj >= i ? 1 : 0);
        float pix = s->ag[i * 8 + 0], piy = s->ag[i * 8 + 1];
        float hix = s->ag[i * 8 + 2], hiy = s->ag[i * 8 + 3];
        float dx = s->ag[j * 8 + 0] - pix, dy = s->ag[j * 8 + 1] - piy;
        float dist = sqrtf(dx * dx + dy * dy);
        float ha = atan2f(hiy, hix);
        float ang = wrapf(atan2f(dy, dx) - ha);
        float gx = s->ag[j * 8 + 6] - pix, gy = s->ag[j * 8 + 7] - piy;
        float gd = sqrtf(gx * gx + gy * gy);
        float ga = wrapf(atan2f(gy, gx) - ha);
        float* e10 = &s->e10[jj * E10S];
        e10[0] = dist / 12.0f;
        e10[1] = cosf(ang);  e10[2] = sinf(ang);
        e10[3] = s->ag[j * 8 + 2];  e10[4] = s->ag[j * 8 + 3];
        e10[5] = s->ag[j * 8 + 4];  e10[6] = s->ag[j * 8 + 5];
        e10[7] = gd;  e10[8] = cosf(ga);  e10[9] = sinf(ga);
        e10[10] = 0.f;  e10[11] = 0.f;
        out[O3 + r * 31 + jj] = dist;
    }
    __syncthreads();

    // ---- k_feat = lrelu(e10 @ k_w) into smem (plain, pad row 31) ----
    {
        float kw[10];
#pragma unroll
        for (int f = 0; f < 10; f++) kw[f] = kw_g[f * 256 + t];
        for (int jj = 0; jj < MJ; jj++) {
            const float* e = &s->e10[jj * E10S];
            float4 p0 = *reinterpret_cast<const float4*>(e);
            float4 p1 = *reinterpret_cast<const float4*>(e + 4);
            float2 p2 = *reinterpret_cast<const float2*>(e + 8);
            float a = p0.x * kw[0] + p0.y * kw[1] + p0.z * kw[2] + p0.w * kw[3]
                    + p1.x * kw[4] + p1.y * kw[5] + p1.z * kw[6] + p1.w * kw[7]
                    + p2.x * kw[8] + p2.y * kw[9];
            s->kf[jj * 256 + t] = lrelu(a);
        }
        s->kf[31 * 256 + t] = 0.f;
    }

    // ---- hard logits via folded W2e: interchanged (u outer, jj inner) ----
    {
        float e7r[4][7];
#pragma unroll
        for (int q = 0; q < 4; q++) {
            int jj = w + 8 * q;
            const float* e = &s->e10[(jj < MJ ? jj : 0) * E10S];
            float4 p0 = *reinterpret_cast<const float4*>(e);
            float4 p1 = *reinterpret_cast<const float4*>(e + 4);
            e7r[q][0] = p0.x; e7r[q][1] = p0.y; e7r[q][2] = p0.z; e7r[q][3] = p0.w;
            e7r[q][4] = p1.x; e7r[q][5] = p1.y; e7r[q][6] = p1.z;
        }
        float a0[4] = {0.f, 0.f, 0.f, 0.f};
        float a1[4] = {0.f, 0.f, 0.f, 0.f};
#pragma unroll
        for (int u = 0; u < 8; u++) {
            int c = lane + 32 * u;
            float w0 = hm1_low[0 * 256 + c];
            float w1 = hm1_low[1 * 256 + c];
            float w2 = hm1_low[2 * 256 + c];
            float w3 = hm1_low[3 * 256 + c];
            float w4 = hm1_low[4 * 256 + c];
            float w5 = hm1_low[5 * 256 + c];
            float w6 = hm1_low[6 * 256 + c];
            float aiv = s->ai[c];
            float w20 = g_W2e[c * 2 + 0];
            float w21 = g_W2e[c * 2 + 1];
#pragma unroll
            for (int q = 0; q < 4; q++) {
                float h = aiv
                    + e7r[q][0] * w0 + e7r[q][1] * w1 + e7r[q][2] * w2
                    + e7r[q][3] * w3 + e7r[q][4] * w4 + e7r[q][5] * w5
                    + e7r[q][6] * w6;
                h = fmaxf(h, 0.f);
                a0[q] += h * w20;
                a1[q] += h * w21;
            }
        }
#pragma unroll
        for (int q = 0; q < 4; q++) {
#pragma unroll
            for (int o = 16; o; o >>= 1) {
                a0[q] += __shfl_xor_sync(0xffffffffu, a0[q], o);
                a1[q] += __shfl_xor_sync(0xffffffffu, a1[q], o);
            }
            int jj = w + 8 * q;
            if (lane == 0 && jj < MJ) {
                float l1 = a1[q] + g_b2e[1];
                s->hl[jj * 2 + 0] = a0[q] + g_b2e[0];
                s->hl[jj * 2 + 1] = l1;
                out[O2 + r * 31 + jj] = l1;
            }
        }
    }

    // ---- score GEMM (FFMA2, staged B, float4 A broadcasts) ----
    const int j0 = (t >> 5) * 4;
    const int cA = (t & 31) * 4;
    const int cB = cA + 128;
    ull acc2[4][4] = {};   // [row][pair]: (cA,cA+1),(cA+2,3),(cB,cB+1),(cB+2,3)
    const int c4 = (t & 63) * 4;   // staging column group
    const int kb = t >> 6;         // staging k offset (0..3)

    for (int k0 = 0; k0 < 256; k0 += 32) {
        __syncthreads();   // previous chunk consumed (also orders kf on 1st iter)
#pragma unroll
        for (int kk = kb; kk < 32; kk += 4) {
            *reinterpret_cast<float4*>(&s->bs[kk * 256 + c4]) =
                *reinterpret_cast<const float4*>(&as1_low[(k0 + kk) * 256 + c4]);
        }
        __syncthreads();
#pragma unroll
        for (int kk = 0; kk < 32; kk += 4) {
            // one 16B broadcast per row covers 4 k-steps (1 crossbar cycle)
            float4 A0 = *reinterpret_cast<const float4*>(&s->kf[(j0 + 0) * 256 + k0 + kk]);
            float4 A1 = *reinterpret_cast<const float4*>(&s->kf[(j0 + 1) * 256 + k0 + kk]);
            float4 A2 = *reinterpret_cast<const float4*>(&s->kf[(j0 + 2) * 256 + k0 + kk]);
            float4 A3 = *reinterpret_cast<const float4*>(&s->kf[(j0 + 3) * 256 + k0 + kk]);
            const float* a0p = reinterpret_cast<const float*>(&A0);
            const float* a1p = reinterpret_cast<const float*>(&A1);
            const float* a2p = reinterpret_cast<const float*>(&A2);
            const float* a3p = reinterpret_cast<const float*>(&A3);
#pragma unroll
            for (int u = 0; u < 4; u++) {
                float v0 = a0p[u], v1 = a1p[u], v2 = a2p[u], v3 = a3p[u];
                float2 f0 = make_float2(v0, v0);
                float2 f1 = make_float2(v1, v1);
                float2 f2 = make_float2(v2, v2);
                float2 f3 = make_float2(v3, v3);
                ull a0 = *reinterpret_cast<ull*>(&f0);
                ull a1 = *reinterpret_cast<ull*>(&f1);
                ull a2 = *reinterpret_cast<ull*>(&f2);
                ull a3 = *reinterpret_cast<ull*>(&f3);
                ulonglong2 bA = *reinterpret_cast<const ulonglong2*>(&s->bs[(kk + u) * 256 + cA]);
                ulonglong2 bB = *reinterpret_cast<const ulonglong2*>(&s->bs[(kk + u) * 256 + cB]);
                acc2[0][0] = fma2(a0, bA.x, acc2[0][0]);
                acc2[0][1] = fma2(a0, bA.y, acc2[0][1]);
                acc2[0][2] = fma2(a0, bB.x, acc2[0][2]);
                acc2[0][3] = fma2(a0, bB.y, acc2[0][3]);
                acc2[1][0] = fma2(a1, bA.x, acc2[1][0]);
                acc2[1][1] = fma2(a1, bA.y, acc2[1][1]);
                acc2[1][2] = fma2(a1, bB.x, acc2[1][2]);
                acc2[1][3] = fma2(a1, bB.y, acc2[1][3]);
                acc2[2][0] = fma2(a2, bA.x, acc2[2][0]);
                acc2[2][1] = fma2(a2, bA.y, acc2[2][1]);
                acc2[2][2] = fma2(a2, bB.x, acc2[2][2]);
                acc2[2][3] = fma2(a2, bB.y, acc2[2][3]);
                acc2[3][0] = fma2(a3, bA.x, acc2[3][0]);
                acc2[3][1] = fma2(a3, bA.y, acc2[3][1]);
                acc2[3][2] = fma2(a3, bB.x, acc2[3][2]);
                acc2[3][3] = fma2(a3, bB.y, acc2[3][3]);
            }
        }
    }

    float as2b0 = as2_b[0];
    float qaA[4], qaB[4], s2A[4], s2B[4];
#pragma unroll
    for (int c = 0; c < 4; c++) {
        qaA[c] = s->qa[cA + c];  qaB[c] = s->qa[cB + c];
        s2A[c] = s->as2[cA + c]; s2B[c] = s->as2[cB + c];
    }
#pragma unroll
    for (int jj = 0; jj < 4; jj++) {
        float2 pA0 = *reinterpret_cast<const float2*>(&acc2[jj][0]);
        float2 pA1 = *reinterpret_cast<const float2*>(&acc2[jj][1]);
        float2 pB0 = *reinterpret_cast<const float2*>(&acc2[jj][2]);
        float2 pB1 = *reinterpret_cast<const float2*>(&acc2[jj][3]);
        float aAcc[4] = {pA0.x, pA0.y, pA1.x, pA1.y};
        float bAcc[4] = {pB0.x, pB0.y, pB1.x, pB1.y};
        float sp = 0.f;
#pragma unroll
        for (int c = 0; c < 4; c++) {
            float hA = fmaxf(qaA[c] + aAcc[c], 0.f);
            float hB = fmaxf(qaB[c] + bAcc[c], 0.f);
            sp += hA * s2A[c] + hB * s2B[c];
        }
#pragma unroll
        for (int o = 16; o; o >>= 1) sp += __shfl_xor_sync(0xffffffffu, sp, o);
        if (lane == 0) s->scores[j0 + jj] = sp + as2b0;
    }
    __syncthreads();

    // ---- gumbel softmax, mask, masked softmax, entropy (warp 0) ----
    if (t < 32) {
        int jj = t;
        bool valid = jj < MJ;
        float maskf = 0.f, ms = -1e30f;
        if (valid) {
            unsigned f0 = 2u * ((unsigned)r * 31u + (unsigned)jj);
            unsigned b0 = jax_bits_partitionable(f0);
            unsigned b1_ = jax_bits_partitionable(f0 + 1u);
            float u0 = jax_uniform(b0), u1 = jax_uniform(b1_);
            float gz0 = -logf(-logf(u0)), gz1 = -logf(-logf(u1));
            float z0 = (s->hl[jj * 2 + 0] + gz0) / 0.5f;
            float z1 = (s->hl[jj * 2 + 1] + gz1) / 0.5f;
            float mz = fmaxf(z0, z1);
            float e0 = expf(z0 - mz), e1 = expf(z1 - mz);
            float hw = e1 / (e0 + e1);
            out[O5 + r * 31 + jj] = hw;
            maskf = hw > 0.5f ? 1.f : 0.f;
            float score = s->scores[jj];
            ms = maskf > 0.f ? score : -1e30f;
        }
        float cnt = maskf;
#pragma unroll
        for (int o = 16; o; o >>= 1) cnt += __shfl_xor_sync(0xffffffffu, cnt, o);
        float mx = ms;
#pragma unroll
        for (int o = 16; o; o >>= 1) mx = fmaxf(mx, __shfl_xor_sync(0xffffffffu, mx, o));
        float ev = valid ? expf(ms - mx) : 0.f;
        float se = ev;
#pragma unroll
        for (int o = 16; o; o >>= 1) se += __shfl_xor_sync(0xffffffffu, se, o);
        float soft = (cnt < 1e-6f) ? 0.f : ev / se;
        float comb = soft * maskf;
        float cs = comb;
#pragma unroll
        for (int o = 16; o; o >>= 1) cs += __shfl_xor_sync(0xffffffffu, cs, o);
        float cwn = comb / (cs + 1e-6f);
        float entc = valid ? cwn * logf(cwn + 1e-6f) : 0.f;
        float ent = entc;
#pragma unroll
        for (int o = 16; o; o >>= 1) ent += __shfl_xor_sync(0xffffffffu, ent, o);
        if (jj == 0) g_ent[r] = -ent;
        if (valid) out[O6 + r * 31 + jj] = comb;
        s->comb[jj] = valid ? comb : 0.f;
    }
    __syncthreads();

    // ---- attn_out = sum_j comb_j * lrelu(e10_j @ v_w + v_b) ----
    {
        float vw[10];
#pragma unroll
        for (int f = 0; f < 10; f++) vw[f] = vw_g[f * 256 + t];
        float vb = vb_g[t];
        float a2 = 0.f;
        for (int jj = 0; jj < MJ; jj++) {
            const float* e = &s->e10[jj * E10S];
            float4 p0 = *reinterpret_cast<const float4*>(e);
            float4 p1 = *reinterpret_cast<const float4*>(e + 4);
            float2 p2 = *reinterpret_cast<const float2*>(e + 8);
            float a = vb
                + p0.x * vw[0] + p0.y * vw[1] + p0.z * vw[2] + p0.w * vw[3]
                + p1.x * vw[4] + p1.y * vw[5] + p1.z * vw[6] + p1.w * vw[7]
                + p2.x * vw[8] + p2.y * vw[9];
            a2 += s->comb[jj] * lrelu(a);
        }
        g_X[r * 512 + 256 + t] = a2;
    }
}

// ---------------------------------------------------------------------------
// Deterministic entropy mean reduction
// ---------------------------------------------------------------------------
__global__ void k_final(float* __restrict__ out) {
    __shared__ float sh[256];
    int t = threadIdx.x;
    float a = 0.f;
    for (int i = t; i < BN; i += 256) a += g_ent[i];
    sh[t] = a;
    __syncthreads();
    for (int o = 128; o; o >>= 1) {
        if (t < o) sh[t] += sh[t + o];
        __syncthreads();
    }
    if (t == 0) out[O4] = sh[0] * (1.0f / 8192.0f);
}

// ---------------------------------------------------------------------------
// Launch
// ---------------------------------------------------------------------------
extern "C" void kernel_launch(void* const* d_in, const int* in_sizes, int n_in,
                              void* d_out, int out_size) {
    (void)in_sizes; (void)n_in; (void)out_size;
    const float* emb   = (const float*)d_in[0];
    const float* e1_w  = (const float*)d_in[1];
    const float* e1_b  = (const float*)d_in[2];
    const float* e2_w  = (const float*)d_in[3];
    const float* e2_b  = (const float*)d_in[4];
    const float* hm1_w = (const float*)d_in[5];
    const float* hm1_b = (const float*)d_in[6];
    const float* hm2_w = (const float*)d_in[7];
    const float* hm2_b = (const float*)d_in[8];
    const float* he_w  = (const float*)d_in[9];
    const float* he_b  = (const float*)d_in[10];
    const float* q_w   = (const float*)d_in[11];
    const float* k_w   = (const float*)d_in[12];
    const float* v_w   = (const float*)d_in[13];
    const float* v_b   = (const float*)d_in[14];
    const float* as1_w = (const float*)d_in[15];
    const float* as1_b = (const float*)d_in[16];
    const float* as2_w = (const float*)d_in[17];
    const float* as2_b = (const float*)d_in[18];
    const float* d1_w  = (const float*)d_in[19];
    const float* d1_b  = (const float*)d_in[20];
    const float* d2_w  = (const float*)d_in[21];
    const float* d2_b  = (const float*)d_in[22];
    float* out = (float*)d_out;

    float *pX, *pY, *pAQ, *pWc, *pbc;
    cudaGetSymbolAddress((void**)&pX, g_X);
    cudaGetSymbolAddress((void**)&pY, g_Y);
    cudaGetSymbolAddress((void**)&pAQ, g_AQ);
    cudaGetSymbolAddress((void**)&pWc, g_Wc);
    cudaGetSymbolAddress((void**)&pbc, g_bc);

    cudaFuncSetAttribute(k_edge, cudaFuncAttributeMaxDynamicSharedMemorySize,
                         (int)sizeof(EdgeSmem));

    k_fold_small<<<1, 512>>>(hm2_w, hm2_b, he_w, he_b, hm1_b, as1_b);
    k_fold_wc<<<256, 512>>>(hm1_w, q_w, as1_w);
    k_agent<<<BN / 8, 256>>>(emb, e1_w, e1_b, e2_w, e2_b);

    // AQ = ae @ [hm1_w[:256] | Wqa] + [hm1_b | as1_b]   (M=8192, K=256, N=512)
    gemm_tile<<<dim3(512 / 64, BN / 64), 256>>>(pX, 512, pWc, 512, pbc, pAQ, 512, 256, 0);

    k_edge<<<BN, 256, sizeof(EdgeSmem)>>>(emb, as1_w, as2_w, as2_b,
                                          k_w, v_w, v_b, hm1_w, out);
    k_final<<<1, 256>>>(out);

    gemm_tile<<<dim3(512 / 64, BN / 64), 256>>>(pX, 512, d1_w, 512, d1_b, pY, 512, 512, 2);
    gemm_tile<<<dim3(512 / 64, BN / 64), 256>>>(pY, 512, d2_w, 512, d2_b, out + O1, 512, 512, 2);
}